// round 1
// baseline (speedup 1.0000x reference)
#include <cuda_runtime.h>
#include <math.h>

#define NN 50000
#define EE 400000
#define FNN 128
#define FEE 64
#define HH 128
#define HEADS 4
#define LL 3
#define BB 16

// ---------------- scratch (device globals; no allocation allowed) ----------------
__device__ float g_xA[NN * HH];
__device__ float g_xB[NN * HH];
__device__ float g_xh[(size_t)NN * HH * HEADS];          // [N,4,128]
__device__ float g_als[NN * HEADS];
__device__ float g_ald[NN * HEADS];
__device__ float g_el[(size_t)LL * EE * HEADS];          // per-layer per-edge att_edge logits
__device__ float g_aleloop[LL * HEADS];
__device__ float g_vs[LL * HH * HEADS];
__device__ float g_vd[LL * HH * HEADS];
__device__ float g_ve[LL * HH * HEADS];
__device__ float g_ue[LL * FEE * HEADS];
__device__ float g_be[LL * HEADS];
__device__ float g_meanef[FEE];
__device__ int g_cnt[NN];
__device__ int g_rowstart[NN + 1];
__device__ int g_cursor[NN];
__device__ int g_eid[EE + NN];
__device__ int g_bsum[64];
__device__ int g_boff[64];
__device__ float g_pool[BB * 512];
__device__ int g_pcnt[BB];

// ---------------- generic K=128 SGEMM: C[M x NC] = A[M x 128] @ B[128 x NC] -------
template <int NC>
__global__ void __launch_bounds__(256) gemm_k128(const float* __restrict__ A,
                                                 const float* __restrict__ B,
                                                 float* __restrict__ C, int M) {
    __shared__ float As[16][68];
    __shared__ float Bs[16][64];
    int bm = blockIdx.x, bn = blockIdx.y;
    int tid = threadIdx.x;
    int tx = tid & 15, ty = tid >> 4;
    int row0 = bm * 64, col0 = bn * 64;

    float acc[4][4];
#pragma unroll
    for (int i = 0; i < 4; i++)
#pragma unroll
        for (int j = 0; j < 4; j++) acc[i][j] = 0.f;

    for (int k0 = 0; k0 < 128; k0 += 16) {
#pragma unroll
        for (int i = 0; i < 4; i++) {
            int m = (tid >> 4) + i * 16;
            int k = tid & 15;
            int r = row0 + m;
            As[k][m] = (r < M) ? A[(size_t)r * 128 + k0 + k] : 0.f;
        }
#pragma unroll
        for (int i = 0; i < 4; i++) {
            int k = (tid >> 6) + i * 4;
            int n = tid & 63;
            Bs[k][n] = B[(size_t)(k0 + k) * NC + col0 + n];
        }
        __syncthreads();
#pragma unroll
        for (int kk = 0; kk < 16; kk++) {
            float4 a = *(const float4*)&As[kk][ty * 4];
            float4 b = *(const float4*)&Bs[kk][tx * 4];
            acc[0][0] += a.x * b.x; acc[0][1] += a.x * b.y; acc[0][2] += a.x * b.z; acc[0][3] += a.x * b.w;
            acc[1][0] += a.y * b.x; acc[1][1] += a.y * b.y; acc[1][2] += a.y * b.z; acc[1][3] += a.y * b.w;
            acc[2][0] += a.z * b.x; acc[2][1] += a.z * b.y; acc[2][2] += a.z * b.z; acc[2][3] += a.z * b.w;
            acc[3][0] += a.w * b.x; acc[3][1] += a.w * b.y; acc[3][2] += a.w * b.z; acc[3][3] += a.w * b.w;
        }
        __syncthreads();
    }
#pragma unroll
    for (int i = 0; i < 4; i++) {
        int r = row0 + ty * 4 + i;
        if (r < M) {
#pragma unroll
            for (int j = 0; j < 4; j++)
                C[(size_t)r * NC + col0 + tx * 4 + j] = acc[i][j];
        }
    }
}

// x0 += b_proj + type_table[node_types]
__global__ void k_epi(const float* __restrict__ b_proj, const float* __restrict__ ttab,
                      const int* __restrict__ nt) {
    int idx = blockIdx.x * blockDim.x + threadIdx.x;
    if (idx >= NN * HH) return;
    int n = idx >> 7, c = idx & 127;
    g_xA[idx] += b_proj[c] + ttab[nt[n] * HH + c];
}

// column sums of edge_features (divide by E later)
__global__ void k_meanef(const float* __restrict__ ef) {
    __shared__ float sh[256];
    int t = threadIdx.x;
    float acc = 0.f;
    size_t total = (size_t)EE * FEE;
    for (size_t i = (size_t)blockIdx.x * 256 + t; i < total; i += (size_t)gridDim.x * 256)
        acc += ef[i];
    sh[t] = acc;
    __syncthreads();
    if (t < 64) {
        float v = sh[t] + sh[t + 64] + sh[t + 128] + sh[t + 192];
        atomicAdd(&g_meanef[t], v);  // column of every element this thread read == t
    }
}

// per-layer folded attention vectors
__global__ void k_prep(const float* __restrict__ Wg, const float* __restrict__ Weg,
                       const float* __restrict__ as_, const float* __restrict__ ad_,
                       const float* __restrict__ ae_, const float* __restrict__ Wep,
                       const float* __restrict__ bep) {
    int l = blockIdx.x, j = threadIdx.x;
    for (int h = 0; h < HEADS; h++) {
        const float* wg = Wg + ((size_t)l * HH + j) * (HEADS * HH) + h * HH;
        const float* weg = Weg + ((size_t)l * HH + j) * (HEADS * HH) + h * HH;
        const float* as = as_ + (l * HEADS + h) * HH;
        const float* ad = ad_ + (l * HEADS + h) * HH;
        const float* ae = ae_ + (l * HEADS + h) * HH;
        float s = 0.f, d = 0.f, e = 0.f;
        for (int c = 0; c < HH; c++) {
            s += wg[c] * as[c];
            d += wg[c] * ad[c];
            e += weg[c] * ae[c];
        }
        g_vs[(l * HH + j) * HEADS + h] = s;
        g_vd[(l * HH + j) * HEADS + h] = d;
        g_ve[(l * HH + j) * HEADS + h] = e;
    }
    __syncthreads();
    if (j < FEE) {
        for (int h = 0; h < HEADS; h++) {
            float u = 0.f;
            for (int k = 0; k < HH; k++)
                u += Wep[j * HH + k] * g_ve[(l * HH + k) * HEADS + h];
            g_ue[(l * FEE + j) * HEADS + h] = u;
        }
    }
    if (j < HEADS) {
        float b = 0.f;
        for (int k = 0; k < HH; k++) b += bep[k] * g_ve[(l * HH + k) * HEADS + j];
        g_be[l * HEADS + j] = b;
    }
    __syncthreads();
    if (j < HEADS) {
        float a = g_be[l * HEADS + j];
        for (int k = 0; k < FEE; k++)
            a += (g_meanef[k] / (float)EE) * g_ue[(l * FEE + k) * HEADS + j];
        g_aleloop[l * HEADS + j] = a;
    }
}

// per-edge att_edge logits for all 3 layers in one pass over edge_features
__global__ void __launch_bounds__(256) k_el(const float* __restrict__ ef) {
    __shared__ float ue[LL * FEE * HEADS];
    __shared__ float be[LL * HEADS];
    int t = threadIdx.x;
    for (int i = t; i < LL * FEE * HEADS; i += 256) ue[i] = g_ue[i];
    if (t < LL * HEADS) be[t] = g_be[t];
    __syncthreads();
    int e = blockIdx.x * 256 + t;
    if (e >= EE) return;
    float r[FEE];
    const float4* p = (const float4*)(ef + (size_t)e * FEE);
#pragma unroll
    for (int i = 0; i < FEE / 4; i++) {
        float4 v = p[i];
        r[i * 4] = v.x; r[i * 4 + 1] = v.y; r[i * 4 + 2] = v.z; r[i * 4 + 3] = v.w;
    }
    float acc[LL * HEADS];
#pragma unroll
    for (int i = 0; i < LL * HEADS; i++) acc[i] = be[i];
    for (int k = 0; k < FEE; k++) {
        float rv = r[k];
#pragma unroll
        for (int l = 0; l < LL; l++)
#pragma unroll
            for (int h = 0; h < HEADS; h++)
                acc[l * HEADS + h] += rv * ue[(l * FEE + k) * HEADS + h];
    }
#pragma unroll
    for (int l = 0; l < LL; l++)
#pragma unroll
        for (int h = 0; h < HEADS; h++)
            g_el[((size_t)l * EE + e) * HEADS + h] = acc[l * HEADS + h];
}

// ---------------- CSR build ----------------
__global__ void k_initcnt() {
    int n = blockIdx.x * blockDim.x + threadIdx.x;
    if (n < NN) g_cnt[n] = 1;  // self loop
}
__global__ void k_hist(const int* __restrict__ dst) {
    int e = blockIdx.x * blockDim.x + threadIdx.x;
    if (e < EE) atomicAdd(&g_cnt[dst[e]], 1);
}
__global__ void k_scan1() {
    __shared__ int sh[1024];
    int t = threadIdx.x;
    int i = blockIdx.x * 1024 + t;
    int v = (i < NN) ? g_cnt[i] : 0;
    sh[t] = v;
    __syncthreads();
    for (int off = 1; off < 1024; off <<= 1) {
        int x = (t >= off) ? sh[t - off] : 0;
        __syncthreads();
        sh[t] += x;
        __syncthreads();
    }
    if (i < NN) g_rowstart[i] = sh[t] - v;
    if (t == 1023) g_bsum[blockIdx.x] = sh[1023];
}
__global__ void k_scan2(int nb) {
    __shared__ int sh[64];
    int t = threadIdx.x;
    int v = (t < nb) ? g_bsum[t] : 0;
    sh[t] = v;
    __syncthreads();
    for (int off = 1; off < 64; off <<= 1) {
        int x = (t >= off) ? sh[t - off] : 0;
        __syncthreads();
        sh[t] += x;
        __syncthreads();
    }
    g_boff[t] = sh[t] - v;
}
__global__ void k_scan3() {
    int i = blockIdx.x * 1024 + threadIdx.x;
    if (i < NN) g_rowstart[i] += g_boff[blockIdx.x];
    if (i == 0) g_rowstart[NN] = EE + NN;
}
__global__ void k_scatter(const int* __restrict__ dst) {
    int i = blockIdx.x * blockDim.x + threadIdx.x;
    if (i >= EE + NN) return;
    int d = (i < EE) ? dst[i] : (i - EE);
    int pos = atomicAdd(&g_cursor[d], 1);
    g_eid[pos] = i;
}

// al_s / al_d = x @ [vs|vd]  (folded per-head src/dst logits)
__global__ void __launch_bounds__(128) k_alsd(const float* __restrict__ x, int l) {
    __shared__ float xs[32][132];
    __shared__ float vsd[HH][8];
    int t = threadIdx.x;
    int n0 = blockIdx.x * 32;
    for (int i = t; i < HH * 8; i += 128) {
        int j = i >> 3, h = i & 7;
        vsd[j][h] = (h < 4) ? g_vs[(l * HH + j) * HEADS + h]
                            : g_vd[(l * HH + j) * HEADS + (h - 4)];
    }
    for (int r = 0; r < 32; r++) {
        int n = n0 + r;
        xs[r][t] = (n < NN) ? x[(size_t)n * HH + t] : 0.f;
    }
    __syncthreads();
    for (int o = t; o < 256; o += 128) {
        int nl = o >> 3, h = o & 7;
        float a = 0.f;
#pragma unroll 8
        for (int j = 0; j < HH; j++) a += xs[nl][j] * vsd[j][h];
        int n = n0 + nl;
        if (n < NN) {
            if (h < 4) g_als[n * HEADS + h] = a;
            else g_ald[n * HEADS + (h - 4)] = a;
        }
    }
}

// per-dst-node: segment softmax + weighted aggregation of xh[src] + head-mean +
// bias + residual + LayerNorm + exact GELU
__global__ void __launch_bounds__(128) k_node(int l, const float* __restrict__ xin,
                                              float* __restrict__ xout,
                                              const int* __restrict__ ei0,
                                              const float* __restrict__ gbias,
                                              const float* __restrict__ lng,
                                              const float* __restrict__ lnb) {
    int n = blockIdx.x, t = threadIdx.x;
    int r0 = g_rowstart[n], r1 = g_rowstart[n + 1];
    float ald0 = g_ald[n * 4 + 0], ald1 = g_ald[n * 4 + 1];
    float ald2 = g_ald[n * 4 + 2], ald3 = g_ald[n * 4 + 3];
    float aL0 = g_aleloop[l * 4 + 0], aL1 = g_aleloop[l * 4 + 1];
    float aL2 = g_aleloop[l * 4 + 2], aL3 = g_aleloop[l * 4 + 3];
    const float* el = g_el + (size_t)l * EE * 4;

    float m0 = -1e30f, m1 = -1e30f, m2 = -1e30f, m3 = -1e30f;
    for (int i = r0; i < r1; i++) {
        int e = g_eid[i];
        float a0, a1, a2, a3;
        if (e < EE) {
            int s = ei0[e];
            const float* as = &g_als[s * 4];
            const float* ee = &el[(size_t)e * 4];
            a0 = as[0] + ald0 + ee[0]; a1 = as[1] + ald1 + ee[1];
            a2 = as[2] + ald2 + ee[2]; a3 = as[3] + ald3 + ee[3];
        } else {
            const float* as = &g_als[(e - EE) * 4];
            a0 = as[0] + ald0 + aL0; a1 = as[1] + ald1 + aL1;
            a2 = as[2] + ald2 + aL2; a3 = as[3] + ald3 + aL3;
        }
        a0 = a0 > 0.f ? a0 : 0.2f * a0; a1 = a1 > 0.f ? a1 : 0.2f * a1;
        a2 = a2 > 0.f ? a2 : 0.2f * a2; a3 = a3 > 0.f ? a3 : 0.2f * a3;
        m0 = fmaxf(m0, a0); m1 = fmaxf(m1, a1); m2 = fmaxf(m2, a2); m3 = fmaxf(m3, a3);
    }

    float z0 = 0.f, z1 = 0.f, z2 = 0.f, z3 = 0.f;
    float c0 = 0.f, c1 = 0.f, c2 = 0.f, c3 = 0.f;
    for (int i = r0; i < r1; i++) {
        int e = g_eid[i];
        float a0, a1, a2, a3;
        int s;
        if (e < EE) {
            s = ei0[e];
            const float* as = &g_als[s * 4];
            const float* ee = &el[(size_t)e * 4];
            a0 = as[0] + ald0 + ee[0]; a1 = as[1] + ald1 + ee[1];
            a2 = as[2] + ald2 + ee[2]; a3 = as[3] + ald3 + ee[3];
        } else {
            s = e - EE;
            const float* as = &g_als[s * 4];
            a0 = as[0] + ald0 + aL0; a1 = as[1] + ald1 + aL1;
            a2 = as[2] + ald2 + aL2; a3 = as[3] + ald3 + aL3;
        }
        a0 = a0 > 0.f ? a0 : 0.2f * a0; a1 = a1 > 0.f ? a1 : 0.2f * a1;
        a2 = a2 > 0.f ? a2 : 0.2f * a2; a3 = a3 > 0.f ? a3 : 0.2f * a3;
        float p0 = expf(a0 - m0), p1 = expf(a1 - m1);
        float p2 = expf(a2 - m2), p3 = expf(a3 - m3);
        z0 += p0; z1 += p1; z2 += p2; z3 += p3;
        const float* xr = g_xh + (size_t)s * 512;
        c0 += p0 * xr[t];
        c1 += p1 * xr[128 + t];
        c2 += p2 * xr[256 + t];
        c3 += p3 * xr[384 + t];
    }

    float y = 0.25f * (c0 / (z0 + 1e-16f) + c1 / (z1 + 1e-16f) +
                       c2 / (z2 + 1e-16f) + c3 / (z3 + 1e-16f));
    y += gbias[l * HH + t] + xin[(size_t)n * HH + t];

    __shared__ float red[128];
    __shared__ float s_mu, s_var;
    red[t] = y;
    __syncthreads();
    for (int s = 64; s > 0; s >>= 1) {
        if (t < s) red[t] += red[t + s];
        __syncthreads();
    }
    if (t == 0) s_mu = red[0] * (1.f / 128.f);
    __syncthreads();
    float xc = y - s_mu;
    red[t] = xc * xc;
    __syncthreads();
    for (int s = 64; s > 0; s >>= 1) {
        if (t < s) red[t] += red[t + s];
        __syncthreads();
    }
    if (t == 0) s_var = red[0] * (1.f / 128.f);
    __syncthreads();
    float o = xc * rsqrtf(s_var + 1e-5f) * lng[l * HH + t] + lnb[l * HH + t];
    float g = 0.5f * o * (1.f + erff(o * 0.70710678118654752f));
    xout[(size_t)n * HH + t] = g;
}

// ---------------- pooling ----------------
__global__ void k_pcnt(const int* __restrict__ batch) {
    int n = blockIdx.x * blockDim.x + threadIdx.x;
    if (n < NN) atomicAdd(&g_pcnt[batch[n]], 1);
}
__global__ void __launch_bounds__(128) k_pool(const float* __restrict__ x,
                                              const int* __restrict__ batch,
                                              const int* __restrict__ nt) {
    int t = threadIdx.x;
    int n0 = blockIdx.x * 128;
    int nend = n0 + 128; if (nend > NN) nend = NN;
    float aF = 0.f, aS = 0.f, aX = 0.f, aG = 0.f;
    int curb = -1;
    for (int n = n0; n < nend; n++) {
        int b = batch[n];
        if (b != curb) {
            if (curb >= 0) {
                atomicAdd(&g_pool[curb * 512 + t], aF);
                atomicAdd(&g_pool[curb * 512 + 128 + t], aS);
                atomicAdd(&g_pool[curb * 512 + 256 + t], aX);
                atomicAdd(&g_pool[curb * 512 + 384 + t], aG);
            }
            curb = b; aF = aS = aX = aG = 0.f;
        }
        float v = x[(size_t)n * HH + t];
        int ty = nt[n];
        aG += v;
        if (ty <= 5) aF += v;
        else if (ty <= 20) aS += v;
        else aX += v;
    }
    if (curb >= 0) {
        atomicAdd(&g_pool[curb * 512 + t], aF);
        atomicAdd(&g_pool[curb * 512 + 128 + t], aS);
        atomicAdd(&g_pool[curb * 512 + 256 + t], aX);
        atomicAdd(&g_pool[curb * 512 + 384 + t], aG);
    }
}
__global__ void k_emb(float* __restrict__ out) {
    int i = blockIdx.x * blockDim.x + threadIdx.x;
    if (i >= BB * 512) return;
    int b = i >> 9;
    float c = (float)(g_pcnt[b] > 1 ? g_pcnt[b] : 1);
    out[(size_t)NN * HH + i] = g_pool[i] / c;
}

// ---------------- launch ----------------
extern "C" void kernel_launch(void* const* d_in, const int* in_sizes, int n_in,
                              void* d_out, int out_size) {
    const float* node_features = (const float*)d_in[0];
    const float* edge_features = (const float*)d_in[1];
    const int* node_types = (const int*)d_in[2];
    const int* edge_index = (const int*)d_in[3];
    const int* batch = (const int*)d_in[4];
    const float* W_proj = (const float*)d_in[5];
    const float* b_proj = (const float*)d_in[6];
    const float* type_table = (const float*)d_in[7];
    const float* W_edgeproj = (const float*)d_in[8];
    const float* b_edgeproj = (const float*)d_in[9];
    const float* W_gat = (const float*)d_in[10];
    const float* W_edge_gat = (const float*)d_in[11];
    const float* att_src = (const float*)d_in[12];
    const float* att_dst = (const float*)d_in[13];
    const float* att_edge = (const float*)d_in[14];
    const float* gat_bias = (const float*)d_in[15];
    const float* ln_g = (const float*)d_in[16];
    const float* ln_b = (const float*)d_in[17];
    const int* ei_src = edge_index;
    const int* ei_dst = edge_index + EE;
    float* out = (float*)d_out;

    float *pxA, *pxB, *pxh, *pmean, *ppool;
    int *pcur, *prs, *ppcnt;
    cudaGetSymbolAddress((void**)&pxA, g_xA);
    cudaGetSymbolAddress((void**)&pxB, g_xB);
    cudaGetSymbolAddress((void**)&pxh, g_xh);
    cudaGetSymbolAddress((void**)&pmean, g_meanef);
    cudaGetSymbolAddress((void**)&ppool, g_pool);
    cudaGetSymbolAddress((void**)&pcur, g_cursor);
    cudaGetSymbolAddress((void**)&prs, g_rowstart);
    cudaGetSymbolAddress((void**)&ppcnt, g_pcnt);

    cudaMemsetAsync(pmean, 0, FEE * sizeof(float));
    cudaMemsetAsync(ppool, 0, BB * 512 * sizeof(float));
    cudaMemsetAsync(ppcnt, 0, BB * sizeof(int));

    const int MB = (NN + 63) / 64;  // 782
    {
        dim3 g(MB, HH / 64);
        gemm_k128<HH><<<g, 256>>>(node_features, W_proj, pxA, NN);
    }
    k_epi<<<(NN * HH + 255) / 256, 256>>>(b_proj, type_table, node_types);
    k_meanef<<<256, 256>>>(edge_features);
    k_prep<<<LL, 128>>>(W_gat, W_edge_gat, att_src, att_dst, att_edge, W_edgeproj, b_edgeproj);
    k_el<<<(EE + 255) / 256, 256>>>(edge_features);

    k_initcnt<<<(NN + 255) / 256, 256>>>();
    k_hist<<<(EE + 255) / 256, 256>>>(ei_dst);
    const int NB = (NN + 1023) / 1024;  // 49
    k_scan1<<<NB, 1024>>>();
    k_scan2<<<1, 64>>>(NB);
    k_scan3<<<NB, 1024>>>();
    cudaMemcpyAsync(pcur, prs, NN * sizeof(int), cudaMemcpyDeviceToDevice);
    k_scatter<<<(EE + NN + 255) / 256, 256>>>(ei_dst);

    for (int l = 0; l < LL; l++) {
        const float* xi = (l == 0) ? pxA : ((l == 1) ? pxB : pxA);
        float* xo = (l == 2) ? out : ((l == 0) ? pxB : pxA);
        dim3 g(MB, (HEADS * HH) / 64);
        gemm_k128<HEADS * HH><<<g, 256>>>(xi, W_gat + (size_t)l * HH * HEADS * HH, pxh, NN);
        k_alsd<<<(NN + 31) / 32, 128>>>(xi, l);
        k_node<<<NN, 128>>>(l, xi, xo, ei_src, gat_bias, ln_g, ln_b);
    }

    k_pcnt<<<(NN + 255) / 256, 256>>>(batch);
    k_pool<<<(NN + 127) / 128, 128>>>(out, batch, node_types);
    k_emb<<<(BB * 512 + 255) / 256, 256>>>(out);
}

// round 2
// speedup vs baseline: 1.7954x; 1.7954x over previous
#include <cuda_runtime.h>
#include <math.h>

#define NN 50000
#define EE 400000
#define FNN 128
#define FEE 64
#define HH 128
#define HEADS 4
#define LL 3
#define BB 16
#define EN (EE + NN)

// ---------------- scratch ----------------
__device__ __align__(16) float g_xA[NN * HH];
__device__ __align__(16) float g_xB[NN * HH];
__device__ __align__(16) float g_xh[(size_t)NN * HH * HEADS];   // [N,4,128]
__device__ __align__(16) float g_als[NN * HEADS];
__device__ __align__(16) float g_ald[NN * HEADS];
__device__ __align__(16) float g_el[(size_t)LL * EE * HEADS];
__device__ __align__(16) float g_p[(size_t)EN * HEADS];         // per-CSR-pos exp(leaky(alpha))
__device__ __align__(16) float g_aleloop[LL * HEADS];
__device__ float g_vs[LL * HH * HEADS];
__device__ float g_vd[LL * HH * HEADS];
__device__ float g_ve[LL * HH * HEADS];
__device__ float g_ue[LL * FEE * HEADS];
__device__ float g_be[LL * HEADS];
__device__ float g_meanef[FEE];
__device__ int g_cnt[NN];
__device__ int g_rowstart[NN + 1];
__device__ int g_cursor[NN];
__device__ int g_eid[EN];
__device__ int g_esrc[EN];
__device__ int g_edst[EN];
__device__ int g_bsum[64];
__device__ int g_boff[64];
__device__ float g_pool[BB * 512];
__device__ int g_pcnt[BB];

// ---------------- SGEMM 128x128 tile, double buffered: C[MxNC]=A[Mx128]@B[128xNC]
template <int NC>
__global__ void __launch_bounds__(256) gemm128(const float* __restrict__ A,
                                               const float* __restrict__ B,
                                               float* __restrict__ C, int M) {
    __shared__ float As[2][8][128];
    __shared__ float Bs[2][8][128];
    int tid = threadIdx.x;
    int row0 = blockIdx.x * 128, col0 = blockIdx.y * 128;
    int tx = tid & 15, ty = tid >> 4;
    int arow = tid >> 1, ak = (tid & 1) * 4;
    int bk = tid >> 5, bn = (tid & 31) * 4;

    float acc[8][8];
#pragma unroll
    for (int i = 0; i < 8; i++)
#pragma unroll
        for (int j = 0; j < 8; j++) acc[i][j] = 0.f;

    float4 av, bv;
    {
        int r = row0 + arow;
        av = (r < M) ? *(const float4*)&A[(size_t)r * 128 + ak] : make_float4(0, 0, 0, 0);
        bv = *(const float4*)&B[(size_t)bk * NC + col0 + bn];
    }
    As[0][ak + 0][arow] = av.x; As[0][ak + 1][arow] = av.y;
    As[0][ak + 2][arow] = av.z; As[0][ak + 3][arow] = av.w;
    *(float4*)&Bs[0][bk][bn] = bv;
    __syncthreads();

    int buf = 0;
    for (int k0 = 0; k0 < 128; k0 += 8) {
        if (k0 + 8 < 128) {
            int r = row0 + arow;
            av = (r < M) ? *(const float4*)&A[(size_t)r * 128 + k0 + 8 + ak]
                         : make_float4(0, 0, 0, 0);
            bv = *(const float4*)&B[(size_t)(k0 + 8 + bk) * NC + col0 + bn];
        }
#pragma unroll
        for (int kk = 0; kk < 8; kk++) {
            float4 a0 = *(const float4*)&As[buf][kk][ty * 8];
            float4 a1 = *(const float4*)&As[buf][kk][ty * 8 + 4];
            float4 b0 = *(const float4*)&Bs[buf][kk][tx * 8];
            float4 b1 = *(const float4*)&Bs[buf][kk][tx * 8 + 4];
            float ar[8] = {a0.x, a0.y, a0.z, a0.w, a1.x, a1.y, a1.z, a1.w};
            float br[8] = {b0.x, b0.y, b0.z, b0.w, b1.x, b1.y, b1.z, b1.w};
#pragma unroll
            for (int i = 0; i < 8; i++)
#pragma unroll
                for (int j = 0; j < 8; j++) acc[i][j] += ar[i] * br[j];
        }
        if (k0 + 8 < 128) {
            int nb = buf ^ 1;
            As[nb][ak + 0][arow] = av.x; As[nb][ak + 1][arow] = av.y;
            As[nb][ak + 2][arow] = av.z; As[nb][ak + 3][arow] = av.w;
            *(float4*)&Bs[nb][bk][bn] = bv;
            __syncthreads();
            buf = nb;
        }
    }
#pragma unroll
    for (int i = 0; i < 8; i++) {
        int r = row0 + ty * 8 + i;
        if (r < M) {
            *(float4*)&C[(size_t)r * NC + col0 + tx * 8] =
                make_float4(acc[i][0], acc[i][1], acc[i][2], acc[i][3]);
            *(float4*)&C[(size_t)r * NC + col0 + tx * 8 + 4] =
                make_float4(acc[i][4], acc[i][5], acc[i][6], acc[i][7]);
        }
    }
}

// x0 += b_proj + type_table[node_types]
__global__ void k_epi(const float* __restrict__ b_proj, const float* __restrict__ ttab,
                      const int* __restrict__ nt) {
    int idx = blockIdx.x * blockDim.x + threadIdx.x;
    if (idx >= NN * HH) return;
    int n = idx >> 7, c = idx & 127;
    g_xA[idx] += b_proj[c] + ttab[nt[n] * HH + c];
}

// column sums of edge_features
__global__ void k_meanef(const float* __restrict__ ef) {
    __shared__ float sh[256];
    int t = threadIdx.x;
    float acc = 0.f;
    size_t total = (size_t)EE * FEE;
    for (size_t i = (size_t)blockIdx.x * 256 + t; i < total; i += (size_t)gridDim.x * 256)
        acc += ef[i];
    sh[t] = acc;
    __syncthreads();
    if (t < 64) {
        float v = sh[t] + sh[t + 64] + sh[t + 128] + sh[t + 192];
        atomicAdd(&g_meanef[t], v);
    }
}

__device__ __forceinline__ float warp_sum(float v) {
#pragma unroll
    for (int off = 16; off > 0; off >>= 1) v += __shfl_xor_sync(0xffffffffu, v, off);
    return v;
}

// vs/vd/ve: one block per (l,j), warp per head
__global__ void __launch_bounds__(128) k_prep1(const float* __restrict__ Wg,
                                               const float* __restrict__ Weg,
                                               const float* __restrict__ as_,
                                               const float* __restrict__ ad_,
                                               const float* __restrict__ ae_) {
    int b = blockIdx.x;
    int l = b >> 7, j = b & 127;
    int h = threadIdx.x >> 5, lane = threadIdx.x & 31;
    const float* wg = Wg + ((size_t)(l * HH + j)) * (HEADS * HH) + h * HH;
    const float* weg = Weg + ((size_t)(l * HH + j)) * (HEADS * HH) + h * HH;
    const float* as = as_ + (l * HEADS + h) * HH;
    const float* ad = ad_ + (l * HEADS + h) * HH;
    const float* ae = ae_ + (l * HEADS + h) * HH;
    float s = 0.f, d = 0.f, e = 0.f;
#pragma unroll
    for (int m = 0; m < 4; m++) {
        int c = lane + m * 32;
        float w = wg[c];
        s += w * as[c];
        d += w * ad[c];
        e += weg[c] * ae[c];
    }
    s = warp_sum(s); d = warp_sum(d); e = warp_sum(e);
    if (lane == 0) {
        g_vs[(l * HH + j) * HEADS + h] = s;
        g_vd[(l * HH + j) * HEADS + h] = d;
        g_ve[(l * HH + j) * HEADS + h] = e;
    }
}

// ue = W_edgeproj @ ve
__global__ void __launch_bounds__(128) k_prep2(const float* __restrict__ Wep) {
    int b = blockIdx.x;
    int l = b / FEE, j = b % FEE;
    int h = threadIdx.x >> 5, lane = threadIdx.x & 31;
    float u = 0.f;
#pragma unroll
    for (int m = 0; m < 4; m++) {
        int k = lane + m * 32;
        u += Wep[j * HH + k] * g_ve[(l * HH + k) * HEADS + h];
    }
    u = warp_sum(u);
    if (lane == 0) g_ue[(l * FEE + j) * HEADS + h] = u;
}

// be = b_edgeproj @ ve; aleloop = be + mean(ef) @ ue
__global__ void __launch_bounds__(128) k_prep3(const float* __restrict__ bep) {
    int l = blockIdx.x;
    int h = threadIdx.x >> 5, lane = threadIdx.x & 31;
    float bsum = 0.f;
#pragma unroll
    for (int m = 0; m < 4; m++) {
        int k = lane + m * 32;
        bsum += bep[k] * g_ve[(l * HH + k) * HEADS + h];
    }
    float asum = 0.f;
#pragma unroll
    for (int m = 0; m < 2; m++) {
        int k = lane + m * 32;
        asum += (g_meanef[k] * (1.f / (float)EE)) * g_ue[(l * FEE + k) * HEADS + h];
    }
    bsum = warp_sum(bsum);
    asum = warp_sum(asum);
    if (lane == 0) {
        g_be[l * HEADS + h] = bsum;
        g_aleloop[l * HEADS + h] = bsum + asum;
    }
}

// per-edge att_edge logits for all 3 layers
__global__ void __launch_bounds__(256) k_el(const float* __restrict__ ef) {
    __shared__ float ue[LL * FEE * HEADS];
    __shared__ float be[LL * HEADS];
    int t = threadIdx.x;
    for (int i = t; i < LL * FEE * HEADS; i += 256) ue[i] = g_ue[i];
    if (t < LL * HEADS) be[t] = g_be[t];
    __syncthreads();
    int e = blockIdx.x * 256 + t;
    if (e >= EE) return;
    float r[FEE];
    const float4* p = (const float4*)(ef + (size_t)e * FEE);
#pragma unroll
    for (int i = 0; i < FEE / 4; i++) {
        float4 v = p[i];
        r[i * 4] = v.x; r[i * 4 + 1] = v.y; r[i * 4 + 2] = v.z; r[i * 4 + 3] = v.w;
    }
    float acc[LL * HEADS];
#pragma unroll
    for (int i = 0; i < LL * HEADS; i++) acc[i] = be[i];
    for (int k = 0; k < FEE; k++) {
        float rv = r[k];
#pragma unroll
        for (int l = 0; l < LL; l++)
#pragma unroll
            for (int h = 0; h < HEADS; h++)
                acc[l * HEADS + h] += rv * ue[(l * FEE + k) * HEADS + h];
    }
#pragma unroll
    for (int l = 0; l < LL; l++)
#pragma unroll
        for (int h = 0; h < HEADS; h++)
            g_el[((size_t)l * EE + e) * HEADS + h] = acc[l * HEADS + h];
}

// ---------------- CSR build ----------------
__global__ void k_initcnt() {
    int n = blockIdx.x * blockDim.x + threadIdx.x;
    if (n < NN) g_cnt[n] = 1;
}
__global__ void k_hist(const int* __restrict__ dst) {
    int e = blockIdx.x * blockDim.x + threadIdx.x;
    if (e < EE) atomicAdd(&g_cnt[dst[e]], 1);
}
__global__ void k_scan1() {
    __shared__ int sh[1024];
    int t = threadIdx.x;
    int i = blockIdx.x * 1024 + t;
    int v = (i < NN) ? g_cnt[i] : 0;
    sh[t] = v;
    __syncthreads();
    for (int off = 1; off < 1024; off <<= 1) {
        int x = (t >= off) ? sh[t - off] : 0;
        __syncthreads();
        sh[t] += x;
        __syncthreads();
    }
    if (i < NN) g_rowstart[i] = sh[t] - v;
    if (t == 1023) g_bsum[blockIdx.x] = sh[1023];
}
__global__ void k_scan2(int nb) {
    __shared__ int sh[64];
    int t = threadIdx.x;
    int v = (t < nb) ? g_bsum[t] : 0;
    sh[t] = v;
    __syncthreads();
    for (int off = 1; off < 64; off <<= 1) {
        int x = (t >= off) ? sh[t - off] : 0;
        __syncthreads();
        sh[t] += x;
        __syncthreads();
    }
    g_boff[t] = sh[t] - v;
}
__global__ void k_scan3() {
    int i = blockIdx.x * 1024 + threadIdx.x;
    if (i < NN) g_rowstart[i] += g_boff[blockIdx.x];
    if (i == 0) g_rowstart[NN] = EN;
}
__global__ void k_scatter(const int* __restrict__ src, const int* __restrict__ dst) {
    int i = blockIdx.x * blockDim.x + threadIdx.x;
    if (i >= EN) return;
    int d, s;
    if (i < EE) { d = dst[i]; s = src[i]; }
    else { d = i - EE; s = i - EE; }
    int pos = atomicAdd(&g_cursor[d], 1);
    g_eid[pos] = i;
    g_esrc[pos] = s;
    g_edst[pos] = d;
}

// al_s / al_d = x @ [vs|vd]
__global__ void __launch_bounds__(128) k_alsd(const float* __restrict__ x, int l) {
    __shared__ float xs[32][132];
    __shared__ float vsd[HH][8];
    int t = threadIdx.x;
    int n0 = blockIdx.x * 32;
    for (int i = t; i < HH * 8; i += 128) {
        int j = i >> 3, h = i & 7;
        vsd[j][h] = (h < 4) ? g_vs[(l * HH + j) * HEADS + h]
                            : g_vd[(l * HH + j) * HEADS + (h - 4)];
    }
    for (int r = 0; r < 32; r++) {
        int n = n0 + r;
        xs[r][t] = (n < NN) ? x[(size_t)n * HH + t] : 0.f;
    }
    __syncthreads();
    for (int o = t; o < 256; o += 128) {
        int nl = o >> 3, h = o & 7;
        float a = 0.f;
#pragma unroll 8
        for (int j = 0; j < HH; j++) a += xs[nl][j] * vsd[j][h];
        int n = n0 + nl;
        if (n < NN) {
            if (h < 4) g_als[n * HEADS + h] = a;
            else g_ald[n * HEADS + (h - 4)] = a;
        }
    }
}

// p = exp(leakyrelu(alpha)) per CSR position (all heads)
__global__ void __launch_bounds__(256) k_alpha(int l) {
    int i = blockIdx.x * 256 + threadIdx.x;
    if (i >= EN) return;
    int e = g_eid[i];
    int s = g_esrc[i];
    int d = g_edst[i];
    float4 as = *(const float4*)&g_als[s * 4];
    float4 ad = *(const float4*)&g_ald[d * 4];
    float4 ee;
    if (e < EE) ee = *(const float4*)&g_el[((size_t)l * EE + e) * 4];
    else ee = *(const float4*)&g_aleloop[l * 4];
    float a0 = as.x + ad.x + ee.x;
    float a1 = as.y + ad.y + ee.y;
    float a2 = as.z + ad.z + ee.z;
    float a3 = as.w + ad.w + ee.w;
    a0 = a0 > 0.f ? a0 : 0.2f * a0;
    a1 = a1 > 0.f ? a1 : 0.2f * a1;
    a2 = a2 > 0.f ? a2 : 0.2f * a2;
    a3 = a3 > 0.f ? a3 : 0.2f * a3;
    float4 pv = make_float4(__expf(a0), __expf(a1), __expf(a2), __expf(a3));
    *(float4*)&g_p[(size_t)i * 4] = pv;
}

// per-dst-node aggregation + head-mean + bias + residual + LN + GELU
__global__ void __launch_bounds__(128) k_node(int l, const float* __restrict__ xin,
                                              float* __restrict__ xout,
                                              const float* __restrict__ gbias,
                                              const float* __restrict__ lng,
                                              const float* __restrict__ lnb) {
    int n = blockIdx.x, t = threadIdx.x;
    int h = t >> 5, lane = t & 31;
    int r0 = g_rowstart[n], r1 = g_rowstart[n + 1];

    float cx = 0.f, cy = 0.f, cz = 0.f, cw = 0.f, z = 0.f;
    const size_t off = (size_t)h * 128 + lane * 4;

    int s_next = 0; float p_next = 0.f;
    if (r0 < r1) { s_next = g_esrc[r0]; p_next = g_p[(size_t)r0 * 4 + h]; }
    for (int i = r0; i < r1; i++) {
        int s = s_next; float p = p_next;
        if (i + 1 < r1) { s_next = g_esrc[i + 1]; p_next = g_p[(size_t)(i + 1) * 4 + h]; }
        float4 xr = *(const float4*)&g_xh[(size_t)s * 512 + off];
        z += p;
        cx += p * xr.x; cy += p * xr.y; cz += p * xr.z; cw += p * xr.w;
    }
    float inv = 1.f / (z + 1e-16f);

    __shared__ float acc[HEADS][HH];
    acc[h][lane * 4 + 0] = cx * inv;
    acc[h][lane * 4 + 1] = cy * inv;
    acc[h][lane * 4 + 2] = cz * inv;
    acc[h][lane * 4 + 3] = cw * inv;
    __syncthreads();

    float y = 0.25f * (acc[0][t] + acc[1][t] + acc[2][t] + acc[3][t]) +
              gbias[l * HH + t] + xin[(size_t)n * HH + t];

    __shared__ float redA[4], redB[4];
    float v = warp_sum(y);
    if (lane == 0) redA[h] = v;
    __syncthreads();
    float mu = (redA[0] + redA[1] + redA[2] + redA[3]) * (1.f / 128.f);
    float xc = y - mu;
    float w = warp_sum(xc * xc);
    if (lane == 0) redB[h] = w;
    __syncthreads();
    float var = (redB[0] + redB[1] + redB[2] + redB[3]) * (1.f / 128.f);
    float o = xc * rsqrtf(var + 1e-5f) * lng[l * HH + t] + lnb[l * HH + t];
    float g = 0.5f * o * (1.f + erff(o * 0.70710678118654752f));
    xout[(size_t)n * HH + t] = g;
}

// ---------------- pooling ----------------
__global__ void k_pcnt(const int* __restrict__ batch) {
    int n = blockIdx.x * blockDim.x + threadIdx.x;
    if (n < NN) atomicAdd(&g_pcnt[batch[n]], 1);
}
__global__ void __launch_bounds__(128) k_pool(const float* __restrict__ x,
                                              const int* __restrict__ batch,
                                              const int* __restrict__ nt) {
    int t = threadIdx.x;
    int n0 = blockIdx.x * 128;
    int nend = n0 + 128; if (nend > NN) nend = NN;
    float aF = 0.f, aS = 0.f, aX = 0.f, aG = 0.f;
    int curb = -1;
    for (int n = n0; n < nend; n++) {
        int b = batch[n];
        if (b != curb) {
            if (curb >= 0) {
                atomicAdd(&g_pool[curb * 512 + t], aF);
                atomicAdd(&g_pool[curb * 512 + 128 + t], aS);
                atomicAdd(&g_pool[curb * 512 + 256 + t], aX);
                atomicAdd(&g_pool[curb * 512 + 384 + t], aG);
            }
            curb = b; aF = aS = aX = aG = 0.f;
        }
        float v = x[(size_t)n * HH + t];
        int ty = nt[n];
        aG += v;
        if (ty <= 5) aF += v;
        else if (ty <= 20) aS += v;
        else aX += v;
    }
    if (curb >= 0) {
        atomicAdd(&g_pool[curb * 512 + t], aF);
        atomicAdd(&g_pool[curb * 512 + 128 + t], aS);
        atomicAdd(&g_pool[curb * 512 + 256 + t], aX);
        atomicAdd(&g_pool[curb * 512 + 384 + t], aG);
    }
}
__global__ void k_emb(float* __restrict__ out) {
    int i = blockIdx.x * blockDim.x + threadIdx.x;
    if (i >= BB * 512) return;
    int b = i >> 9;
    float c = (float)(g_pcnt[b] > 1 ? g_pcnt[b] : 1);
    out[(size_t)NN * HH + i] = g_pool[i] / c;
}

// ---------------- launch ----------------
extern "C" void kernel_launch(void* const* d_in, const int* in_sizes, int n_in,
                              void* d_out, int out_size) {
    const float* node_features = (const float*)d_in[0];
    const float* edge_features = (const float*)d_in[1];
    const int* node_types = (const int*)d_in[2];
    const int* edge_index = (const int*)d_in[3];
    const int* batch = (const int*)d_in[4];
    const float* W_proj = (const float*)d_in[5];
    const float* b_proj = (const float*)d_in[6];
    const float* type_table = (const float*)d_in[7];
    const float* W_edgeproj = (const float*)d_in[8];
    const float* b_edgeproj = (const float*)d_in[9];
    const float* W_gat = (const float*)d_in[10];
    const float* W_edge_gat = (const float*)d_in[11];
    const float* att_src = (const float*)d_in[12];
    const float* att_dst = (const float*)d_in[13];
    const float* att_edge = (const float*)d_in[14];
    const float* gat_bias = (const float*)d_in[15];
    const float* ln_g = (const float*)d_in[16];
    const float* ln_b = (const float*)d_in[17];
    const int* ei_src = edge_index;
    const int* ei_dst = edge_index + EE;
    float* out = (float*)d_out;

    float *pxA, *pxB, *pxh, *pmean, *ppool;
    int *pcur, *prs, *ppcnt;
    cudaGetSymbolAddress((void**)&pxA, g_xA);
    cudaGetSymbolAddress((void**)&pxB, g_xB);
    cudaGetSymbolAddress((void**)&pxh, g_xh);
    cudaGetSymbolAddress((void**)&pmean, g_meanef);
    cudaGetSymbolAddress((void**)&ppool, g_pool);
    cudaGetSymbolAddress((void**)&pcur, g_cursor);
    cudaGetSymbolAddress((void**)&prs, g_rowstart);
    cudaGetSymbolAddress((void**)&ppcnt, g_pcnt);

    cudaMemsetAsync(pmean, 0, FEE * sizeof(float));
    cudaMemsetAsync(ppool, 0, BB * 512 * sizeof(float));
    cudaMemsetAsync(ppcnt, 0, BB * sizeof(int));

    const int MB = (NN + 127) / 128;  // 391
    {
        dim3 g(MB, 1);
        gemm128<HH><<<g, 256>>>(node_features, W_proj, pxA, NN);
    }
    k_epi<<<(NN * HH + 255) / 256, 256>>>(b_proj, type_table, node_types);
    k_meanef<<<256, 256>>>(edge_features);
    k_prep1<<<LL * HH, 128>>>(W_gat, W_edge_gat, att_src, att_dst, att_edge);
    k_prep2<<<LL * FEE, 128>>>(W_edgeproj);
    k_prep3<<<LL, 128>>>(b_edgeproj);
    k_el<<<(EE + 255) / 256, 256>>>(edge_features);

    k_initcnt<<<(NN + 255) / 256, 256>>>();
    k_hist<<<(EE + 255) / 256, 256>>>(ei_dst);
    const int NB = (NN + 1023) / 1024;  // 49
    k_scan1<<<NB, 1024>>>();
    k_scan2<<<1, 64>>>(NB);
    k_scan3<<<NB, 1024>>>();
    cudaMemcpyAsync(pcur, prs, NN * sizeof(int), cudaMemcpyDeviceToDevice);
    k_scatter<<<(EN + 255) / 256, 256>>>(ei_src, ei_dst);

    for (int l = 0; l < LL; l++) {
        const float* xi = (l == 0) ? pxA : ((l == 1) ? pxB : pxA);
        float* xo = (l == 2) ? out : ((l == 0) ? pxB : pxA);
        dim3 g(MB, (HEADS * HH) / 128);
        gemm128<HEADS * HH><<<g, 256>>>(xi, W_gat + (size_t)l * HH * HEADS * HH, pxh, NN);
        k_alsd<<<(NN + 31) / 32, 128>>>(xi, l);
        k_alpha<<<(EN + 255) / 256, 256>>>(l);
        k_node<<<NN, 128>>>(l, xi, xo, gat_bias, ln_g, ln_b);
    }

    k_pcnt<<<(NN + 255) / 256, 256>>>(batch);
    k_pool<<<(NN + 127) / 128, 128>>>(out, batch, node_types);
    k_emb<<<(BB * 512 + 255) / 256, 256>>>(out);
}